// round 16
// baseline (speedup 1.0000x reference)
#include <cuda_runtime.h>
#include <cuda_fp16.h>
#include <cstdint>

// Problem constants
#define NMB 32          // N*M
#define TLEN 300
#define VJ 25
#define CH 64
#define KT 9
#define NSKEL (NMB*TLEN)          // 9600 skeletons

// -------- scratch --------
__device__ __half g_xg[NMB*VJ*TLEN*CH];            // GCN output (nm,v,t,c), fp16
__device__ __align__(16) uint32_t g_w2[KT*CH*36];  // conv W packed [tap][co][p(ci/2)] half2
__device__ __align__(16) uint32_t g_gw2[CH*36];    // GCN W packed [co][q(ci/2)] half2
__device__ __align__(16) uint32_t g_ah2[32*20];    // normalized adjacency fp16 [v][u-pair], padded
__device__ float g_scale[CH];                      // BN fold: gamma/sqrt(var+eps)
__device__ float g_shift[CH];                      // (conv_b - mean)*scale + beta
__device__ unsigned int g_unit_ctr;                // conv work queue (reset by prep each launch)

__device__ __forceinline__ void cp_async16(void* dst_smem, const void* src) {
    uint32_t d = (uint32_t)__cvta_generic_to_shared(dst_smem);
    asm volatile("cp.async.ca.shared.global [%0], [%1], 16;" :: "r"(d), "l"(src));
}
#define CP_COMMIT() asm volatile("cp.async.commit_group;")
#define CP_WAIT0()  asm volatile("cp.async.wait_group 0;")
#define CP_WAIT1()  asm volatile("cp.async.wait_group 1;")

__device__ __forceinline__ void mma_f16(float* d, const uint32_t* a, uint32_t b0, uint32_t b1) {
    asm volatile("mma.sync.aligned.m16n8k16.row.col.f32.f16.f16.f32 "
        "{%0,%1,%2,%3}, {%4,%5,%6,%7}, {%8,%9}, {%0,%1,%2,%3};"
        : "+f"(d[0]), "+f"(d[1]), "+f"(d[2]), "+f"(d[3])
        : "r"(a[0]), "r"(a[1]), "r"(a[2]), "r"(a[3]), "r"(b0), "r"(b1));
}

__device__ __forceinline__ void ldsm_x4(uint32_t* r, uint32_t saddr) {
    asm volatile("ldmatrix.sync.aligned.m8n8.x4.shared.b16 {%0,%1,%2,%3}, [%4];"
        : "=r"(r[0]), "=r"(r[1]), "=r"(r[2]), "=r"(r[3]) : "r"(saddr));
}

#define CONV_GRID 444
#define CONV_UNITS (NMB*VJ*2)   // 1600

// ============================ prep ============================
__global__ void prep_kernel(const float* __restrict__ adj,
                            const float* __restrict__ gcn_w,
                            const float* __restrict__ conv_w,
                            const float* __restrict__ conv_b,
                            const float* __restrict__ bn_gamma,
                            const float* __restrict__ bn_beta,
                            const float* __restrict__ bn_mean,
                            const float* __restrict__ bn_var) {
    const int tid = threadIdx.x;
    const int gtid = blockIdx.x * blockDim.x + tid;
    const int gstride = gridDim.x * blockDim.x;

    if (blockIdx.x == 0) {
        if (tid == 0) g_unit_ctr = CONV_GRID;   // reset queue each launch (graph-replay safe)
        __shared__ float norm[VJ];
        if (tid < VJ) {
            float s = 0.f;
            for (int u = 0; u < VJ; u++) s += adj[tid*VJ + u];
            norm[tid] = rsqrtf(s);
        }
        __syncthreads();
        for (int i = tid; i < 32*20; i += blockDim.x) {
            int v = i / 20, q = i % 20;
            uint32_t val = 0;
            if (v < VJ && q < 16) {
                int u0 = 2*q, u1 = 2*q + 1;
                float a0 = (u0 < VJ) ? norm[v]*adj[v*VJ+u0]*norm[u0] : 0.f;
                float a1 = (u1 < VJ) ? norm[v]*adj[v*VJ+u1]*norm[u1] : 0.f;
                __half2 h2 = __floats2half2_rn(a0, a1);
                val = *(uint32_t*)&h2;
            }
            g_ah2[i] = val;
        }
        if (tid < CH) {
            float inv = bn_gamma[tid] * rsqrtf(bn_var[tid] + 1e-5f);
            g_scale[tid] = inv;
            g_shift[tid] = (conv_b[tid] - bn_mean[tid]) * inv + bn_beta[tid];
        }
    }
    for (int i = gtid; i < CH*36; i += gstride) {
        int co = i / 36, q = i % 36;
        uint32_t val = 0;
        if (q < 32) {
            __half2 h2 = __floats2half2_rn(gcn_w[(2*q)*CH + co], gcn_w[(2*q+1)*CH + co]);
            val = *(uint32_t*)&h2;
        }
        g_gw2[i] = val;
    }
    for (int i = gtid; i < KT*CH*36; i += gstride) {
        int k   = i / (CH*36);
        int rem = i - k*(CH*36);
        int co  = rem / 36;
        int p   = rem % 36;
        uint32_t val = 0;
        if (p < 32) {
            float w0 = conv_w[(co*CH + 2*p    )*KT + k];
            float w1 = conv_w[(co*CH + 2*p + 1)*KT + k];
            __half2 h2 = __floats2half2_rn(w0, w1);
            val = *(uint32_t*)&h2;
        }
        g_w2[i] = val;
    }
}

// ============================ GCN (R15 proven: staged coalesced epilogue) ============================
#define HS_STR 36
#define WS_STR 36
#define HWT_STR 20
#define AH_STR 20
#define GCN_S 4
#define GCN_GRID 600
#define GCN_ITERS 4

__global__ __launch_bounds__(256, 4)
void gcn_kernel(const float* __restrict__ h,
                const float* __restrict__ gcn_b) {
    extern __shared__ __align__(16) char smraw[];
    uint32_t* hs2 = (uint32_t*)smraw;                 // 128*36 (reused as x-staging after GEMM1)
    uint32_t* Ws2 = hs2 + 128*HS_STR;                 // 64*36
    uint32_t* hwT = Ws2 + CH*WS_STR;                  // 256*20
    uint32_t* ah2 = hwT + 256*HWT_STR;                // 32*20
    float*    gb  = (float*)(ah2 + 32*AH_STR);        // 64

    const int tid = threadIdx.x;

    for (int i = tid; i < CH*WS_STR/4; i += 256)
        cp_async16(&Ws2[i*4], &g_gw2[i*4]);
    for (int i = tid; i < 32*AH_STR/4; i += 256)
        cp_async16(&ah2[i*4], &g_ah2[i*4]);
    if (tid < 16)
        cp_async16(&gb[tid*4], &gcn_b[tid*4]);
    CP_COMMIT();
    CP_WAIT0();

    const int lane = tid & 31, w = tid >> 5;
    const int gID = lane >> 2, tig = lane & 3;

    for (int it = 0; it < GCN_ITERS; it++) {
        const int g0 = (blockIdx.x + it*GCN_GRID) * GCN_S;
        const float* hbase = h + (long long)g0 * VJ * CH;

        for (int i = tid; i < 128*16; i += 256) {
            int r = i >> 4, c4 = (i & 15) * 4;
            int s = r >> 5, vv = r & 31;
            uint2 val = make_uint2(0, 0);
            if (vv < VJ) {
                float4 v = *(const float4*)&hbase[(s*VJ + vv)*CH + c4];
                __half2 p0 = __floats2half2_rn(v.x, v.y);
                __half2 p1 = __floats2half2_rn(v.z, v.w);
                val = make_uint2(*(uint32_t*)&p0, *(uint32_t*)&p1);
            }
            *(uint2*)&hs2[r*HS_STR + (i & 15)*2] = val;
        }
        __syncthreads();

        {
            const int mt = w & 3;
            const int ng = w >> 2;
            float acc[8][4];
#pragma unroll
            for (int nb = 0; nb < 8; nb++)
#pragma unroll
                for (int j = 0; j < 4; j++) acc[nb][j] = 0.f;
#pragma unroll
            for (int kk = 0; kk < 4; kk++) {
                int abase = (mt*16 + gID)*WS_STR + kk*8 + tig;
                uint32_t a[4];
                a[0] = Ws2[abase];
                a[1] = Ws2[abase + 8*WS_STR];
                a[2] = Ws2[abase + 4];
                a[3] = Ws2[abase + 8*WS_STR + 4];
                const uint32_t* bp = hs2 + (ng*64 + gID)*HS_STR + kk*8 + tig;
#pragma unroll
                for (int nb = 0; nb < 8; nb++) {
                    uint32_t b0 = bp[nb*8*HS_STR];
                    uint32_t b1 = bp[nb*8*HS_STR + 4];
                    mma_f16(acc[nb], a, b0, b1);
                }
            }
#pragma unroll
            for (int nb = 0; nb < 8; nb++) {
                int srow = (ng*2 + (nb >> 2)) * 64 + mt*16 + gID;
                int col  = (nb & 3)*4 + tig;
#pragma unroll
                for (int rr = 0; rr < 2; rr++) {
                    __half2 h2 = __floats2half2_rn(acc[nb][rr*2], acc[nb][rr*2+1]);
                    hwT[(srow + rr*8)*HWT_STR + col] = *(uint32_t*)&h2;
                }
            }
        }
        __syncthreads();

        {
            const int s = w >> 1, mt2 = w & 1;
            float acc[8][4];
#pragma unroll
            for (int nb = 0; nb < 8; nb++)
#pragma unroll
                for (int j = 0; j < 4; j++) acc[nb][j] = 0.f;
#pragma unroll
            for (int kk = 0; kk < 2; kk++) {
                int abase = (mt2*16 + gID)*AH_STR + kk*8 + tig;
                uint32_t a[4];
                a[0] = ah2[abase];
                a[1] = ah2[abase + 8*AH_STR];
                a[2] = ah2[abase + 4];
                a[3] = ah2[abase + 8*AH_STR + 4];
                const uint32_t* bp = hwT + (s*64 + gID)*HWT_STR + kk*8 + tig;
#pragma unroll
                for (int nb = 0; nb < 8; nb++) {
                    uint32_t b0 = bp[nb*8*HWT_STR];
                    uint32_t b1 = bp[nb*8*HWT_STR + 4];
                    mma_f16(acc[nb], a, b0, b1);
                }
            }
#pragma unroll
            for (int nb = 0; nb < 8; nb++) {
                int c = nb*8 + tig*2;
                float2 gbv = *(const float2*)&gb[c];
#pragma unroll
                for (int rr = 0; rr < 2; rr++) {
                    int vv = mt2*16 + gID + rr*8;
                    float x0 = fmaxf(acc[nb][rr*2]   + gbv.x, 0.f);
                    float x1 = fmaxf(acc[nb][rr*2+1] + gbv.y, 0.f);
                    __half2 h2 = __floats2half2_rn(x0, x1);
                    hs2[(s*32 + vv)*HS_STR + nb*4 + tig] = *(uint32_t*)&h2;
                }
            }
        }
        __syncthreads();

        for (int i = tid; i < 100*8; i += 256) {
            int r = i >> 3, chunk = i & 7;
            int s = r / VJ, vv = r - s*VJ;
            uint4 val = *(uint4*)&hs2[(s*32 + vv)*HS_STR + chunk*4];
            int g = g0 + s;
            int nm = g / TLEN, t = g % TLEN;
            *(uint4*)&g_xg[((nm*VJ + vv)*TLEN + t)*CH + chunk*8] = val;
        }
        if (it < GCN_ITERS-1)
            __syncthreads();
    }
}

// ============================ Conv (persistent queue, split async groups) ============================
#define XSTR_H 72          // halves per X row
#define WSTR_U 36          // u32 per W co row
#define XROWS 168
#define CONV_THREADS 160
#define XBUF_B (XROWS*XSTR_H*2)    // 24192 B per X buffer

__global__ __launch_bounds__(CONV_THREADS, 3)
void conv_mma_kernel(const float* __restrict__ h, float* __restrict__ out) {
    extern __shared__ __align__(16) char smraw[];
    __half*   xs0 = (__half*)smraw;                       // X buf 0
    __half*   xs1 = (__half*)(smraw + XBUF_B);            // X buf 1
    uint32_t* wb  = (uint32_t*)(smraw + 2*XBUF_B);        // 2 * 64*36 u32
    __shared__ int s_next;

    const int tid  = threadIdx.x;
    int unit = blockIdx.x;

    // initial fills: X(unit) into buf0, W tap0 into wb[0]
    {
        const __half* xg = g_xg + (long long)(unit >> 1) * TLEN * CH;
        const int tbase = (unit & 1) * 150;
        for (int i = tid; i < XROWS*8; i += CONV_THREADS) {
            int r = i >> 3, c8 = (i & 7) * 8;
            int tg = tbase - 4 + r;
            __half* dst = &xs0[r*XSTR_H + c8];
            if (r < 158 && tg >= 0 && tg < TLEN)
                cp_async16(dst, xg + tg*CH + c8);
            else
                *(float4*)dst = make_float4(0,0,0,0);
        }
        for (int i = tid; i < CH*WSTR_U/4; i += CONV_THREADS)
            cp_async16(&wb[i*4], &g_w2[i*4]);
        CP_COMMIT();
        CP_WAIT0();
    }
    __syncthreads();

    const int lane = tid & 31, w = tid >> 5;
    const int gID = lane >> 2, tig = lane & 3;

    const uint32_t xs032 = (uint32_t)__cvta_generic_to_shared(xs0);
    const uint32_t xs132 = (uint32_t)__cvta_generic_to_shared(xs1);
    const uint32_t wb32  = (uint32_t)__cvta_generic_to_shared(wb);
    const int xrow = ((lane >> 3) & 1) * 8 + (lane & 7);
    const int xkof = (lane >> 4) * 8;
    const uint32_t xoff = (uint32_t)(((w*32 + xrow)*XSTR_H + xkof) * 2);
    const int bco  = (lane & 7) + ((lane >> 4) << 3);
    const int bkof = ((lane >> 3) & 1) * 4;
    const uint32_t bbase = wb32 + (uint32_t)((bco*WSTR_U + bkof) * 4);

    int buf = 0, wpar = 0;

    while (true) {
        if (tid == 0) s_next = (int)atomicAdd(&g_unit_ctr, 1u);
        __syncthreads();
        const int next = s_next;
        const bool has_next = (next < CONV_UNITS);

        const int slab = unit >> 1, half = unit & 1;
        const int nm = slab / VJ, v = slab % VJ;
        const int tbase = half * 150;
        __half* xs_nxt = buf ? xs0 : xs1;
        const uint32_t xbase = (buf ? xs132 : xs032) + xoff;

        float acc[2][8][4];
#pragma unroll
        for (int mt = 0; mt < 2; mt++)
#pragma unroll
            for (int nb = 0; nb < 8; nb++)
#pragma unroll
                for (int j = 0; j < 4; j++) acc[mt][nb][j] = 0.f;

        for (int k = 0; k < KT; k++) {
            const uint32_t wsel = (uint32_t)(((wpar + k) & 1) * (CH*WSTR_U*4));
            // W prefetch: its OWN commit group (small, L2-resident)
            const bool w_more = (k < KT-1) || has_next;
            if (w_more) {
                const int nk = (k < KT-1) ? (k+1) : 0;
                uint32_t* wnext = wb + ((wpar + k + 1) & 1) * CH*WSTR_U;
                const uint32_t* wsrc = g_w2 + nk*CH*WSTR_U;
                for (int i = tid; i < CH*WSTR_U/4; i += CONV_THREADS)
                    cp_async16(&wnext[i*4], &wsrc[i*4]);
                CP_COMMIT();
            }
            // X-chunk prefetch for next unit: separate group, NOT waited per-tap
            if (has_next) {
                int i = k*CONV_THREADS + tid;
                if (i < XROWS*8) {
                    int r = i >> 3, c8 = (i & 7) * 8;
                    int ntb = (next & 1) * 150;
                    int tg = ntb - 4 + r;
                    __half* dst = &xs_nxt[r*XSTR_H + c8];
                    if (r < 158 && tg >= 0 && tg < TLEN)
                        cp_async16(dst, g_xg + (long long)(next >> 1)*TLEN*CH + tg*CH + c8);
                    else
                        *(float4*)dst = make_float4(0,0,0,0);
                }
                CP_COMMIT();
            }

            const uint32_t xk = xbase + (uint32_t)(k * (XSTR_H*2));
#pragma unroll
            for (int kk = 0; kk < 4; kk++) {
                uint32_t a0[4], a1[4];
                ldsm_x4(a0, xk + kk*32);
                ldsm_x4(a1, xk + 16*(XSTR_H*2) + kk*32);
                uint32_t bf[4][4];
#pragma unroll
                for (int p = 0; p < 4; p++)
                    ldsm_x4(bf[p], bbase + wsel + p*(16*WSTR_U*4) + kk*32);
#pragma unroll
                for (int nb = 0; nb < 8; nb++) {
                    uint32_t b0 = bf[nb >> 1][(nb & 1)*2 + 0];
                    uint32_t b1 = bf[nb >> 1][(nb & 1)*2 + 1];
                    mma_f16(acc[0][nb], a0, b0, b1);
                    mma_f16(acc[1][nb], a1, b0, b1);
                }
            }
            if (k < KT-1) {
                // FIFO: wait<=1 forces W(k+1) (+older X chunk), leaves freshest X in flight
                if (has_next) CP_WAIT1(); else CP_WAIT0();
                __syncthreads();
            }
        }

        // epilogue: BN fold + ReLU + residual (X tail chunk + W0' still in flight)
#pragma unroll
        for (int mt = 0; mt < 2; mt++) {
#pragma unroll
            for (int nb = 0; nb < 8; nb++) {
                int co = nb*8 + tig*2;
                float2 scl = *(const float2*)&g_scale[co];
                float2 sft = *(const float2*)&g_shift[co];
#pragma unroll
                for (int rr = 0; rr < 2; rr++) {
                    int tl = w*32 + mt*16 + gID + rr*8;
                    if (tl >= 150) continue;
                    int t = tbase + tl;
                    long long o = (((long long)nm*TLEN + t)*VJ + v)*CH + co;
                    float x0 = fmaxf(acc[mt][nb][rr*2]  *scl.x + sft.x, 0.f);
                    float x1 = fmaxf(acc[mt][nb][rr*2+1]*scl.y + sft.y, 0.f);
                    float2 hv = *(const float2*)&h[o];
                    *(float2*)&out[o] = make_float2(x0 + hv.x, x1 + hv.y);
                }
            }
        }

        if (!has_next) break;
        CP_WAIT0();          // X(next) + W tap0(next) landed
        __syncthreads();
        unit = next;
        buf ^= 1;
        wpar ^= 1;           // 9 taps flip W parity
    }
}

// ============================ launch ============================
extern "C" void kernel_launch(void* const* d_in, const int* in_sizes, int n_in,
                              void* d_out, int out_size) {
    const float* h        = (const float*)d_in[0];
    const float* adj      = (const float*)d_in[1];
    const float* gcn_w    = (const float*)d_in[2];
    const float* gcn_b    = (const float*)d_in[3];
    const float* conv_w   = (const float*)d_in[4];
    const float* conv_b   = (const float*)d_in[5];
    const float* bn_gamma = (const float*)d_in[6];
    const float* bn_beta  = (const float*)d_in[7];
    const float* bn_mean  = (const float*)d_in[8];
    const float* bn_var   = (const float*)d_in[9];
    float* out = (float*)d_out;

    const int gcn_smem  = (128*HS_STR + CH*WS_STR + 256*HWT_STR + 32*AH_STR)*4 + CH*4;  // ~51 KB
    const int conv_smem = 2*XBUF_B + 2*CH*WSTR_U*4;            // 66816 B
    cudaFuncSetAttribute(gcn_kernel,      cudaFuncAttributeMaxDynamicSharedMemorySize, gcn_smem);
    cudaFuncSetAttribute(conv_mma_kernel, cudaFuncAttributeMaxDynamicSharedMemorySize, conv_smem);

    prep_kernel<<<256, 256>>>(adj, gcn_w, conv_w, conv_b, bn_gamma, bn_beta, bn_mean, bn_var);
    gcn_kernel<<<GCN_GRID, 256, gcn_smem>>>(h, gcn_b);
    conv_mma_kernel<<<CONV_GRID, CONV_THREADS, conv_smem>>>(h, out);
}

// round 17
// speedup vs baseline: 1.4284x; 1.4284x over previous
#include <cuda_runtime.h>
#include <cuda_fp16.h>
#include <cstdint>

// Problem constants
#define NMB 32          // N*M
#define TLEN 300
#define VJ 25
#define CH 64
#define KT 9
#define NSKEL (NMB*TLEN)          // 9600 skeletons

// -------- scratch --------
__device__ __half g_xg[NMB*VJ*TLEN*CH];            // GCN output (nm,v,t,c), fp16
__device__ __align__(16) uint32_t g_w2[KT*CH*36];  // conv W packed [tap][co][p(ci/2)] half2
__device__ __align__(16) uint32_t g_gw2[CH*36];    // GCN W packed [co][q(ci/2)] half2
__device__ __align__(16) uint32_t g_ah2[32*20];    // normalized adjacency fp16 [v][u-pair], padded
__device__ float g_scale[CH];                      // BN fold: gamma/sqrt(var+eps)
__device__ float g_shift[CH];                      // (conv_b - mean)*scale + beta
__device__ unsigned int g_gcn_ctr;                 // GCN work queue (reset by prep each launch)

__device__ __forceinline__ void cp_async16(void* dst_smem, const void* src) {
    uint32_t d = (uint32_t)__cvta_generic_to_shared(dst_smem);
    asm volatile("cp.async.ca.shared.global [%0], [%1], 16;" :: "r"(d), "l"(src));
}
#define CP_COMMIT() asm volatile("cp.async.commit_group;")
#define CP_WAIT0()  asm volatile("cp.async.wait_group 0;")

__device__ __forceinline__ void mma_f16(float* d, const uint32_t* a, uint32_t b0, uint32_t b1) {
    asm volatile("mma.sync.aligned.m16n8k16.row.col.f32.f16.f16.f32 "
        "{%0,%1,%2,%3}, {%4,%5,%6,%7}, {%8,%9}, {%0,%1,%2,%3};"
        : "+f"(d[0]), "+f"(d[1]), "+f"(d[2]), "+f"(d[3])
        : "r"(a[0]), "r"(a[1]), "r"(a[2]), "r"(a[3]), "r"(b0), "r"(b1));
}

__device__ __forceinline__ void ldsm_x4(uint32_t* r, uint32_t saddr) {
    asm volatile("ldmatrix.sync.aligned.m8n8.x4.shared.b16 {%0,%1,%2,%3}, [%4];"
        : "=r"(r[0]), "=r"(r[1]), "=r"(r[2]), "=r"(r[3]) : "r"(saddr));
}

// ============================ prep ============================
__global__ void prep_kernel(const float* __restrict__ adj,
                            const float* __restrict__ gcn_w,
                            const float* __restrict__ conv_w,
                            const float* __restrict__ conv_b,
                            const float* __restrict__ bn_gamma,
                            const float* __restrict__ bn_beta,
                            const float* __restrict__ bn_mean,
                            const float* __restrict__ bn_var) {
    const int tid = threadIdx.x;
    const int gtid = blockIdx.x * blockDim.x + tid;
    const int gstride = gridDim.x * blockDim.x;

    if (blockIdx.x == 0) {
        if (tid == 0) g_gcn_ctr = 0;   // reset GCN queue every launch (graph-replay safe)
        __shared__ float norm[VJ];
        if (tid < VJ) {
            float s = 0.f;
            for (int u = 0; u < VJ; u++) s += adj[tid*VJ + u];
            norm[tid] = rsqrtf(s);
        }
        __syncthreads();
        // Ah fp16 pack: g_ah2[v][q] = half2(Ah(v,2q), Ah(v,2q+1)), zero-padded to 32x20
        for (int i = tid; i < 32*20; i += blockDim.x) {
            int v = i / 20, q = i % 20;
            uint32_t val = 0;
            if (v < VJ && q < 16) {
                int u0 = 2*q, u1 = 2*q + 1;
                float a0 = (u0 < VJ) ? norm[v]*adj[v*VJ+u0]*norm[u0] : 0.f;
                float a1 = (u1 < VJ) ? norm[v]*adj[v*VJ+u1]*norm[u1] : 0.f;
                __half2 h2 = __floats2half2_rn(a0, a1);
                val = *(uint32_t*)&h2;
            }
            g_ah2[i] = val;
        }
        if (tid < CH) {
            float inv = bn_gamma[tid] * rsqrtf(bn_var[tid] + 1e-5f);
            g_scale[tid] = inv;
            g_shift[tid] = (conv_b[tid] - bn_mean[tid]) * inv + bn_beta[tid];
        }
    }
    for (int i = gtid; i < CH*36; i += gstride) {
        int co = i / 36, q = i % 36;
        uint32_t val = 0;
        if (q < 32) {
            __half2 h2 = __floats2half2_rn(gcn_w[(2*q)*CH + co], gcn_w[(2*q+1)*CH + co]);
            val = *(uint32_t*)&h2;
        }
        g_gw2[i] = val;
    }
    for (int i = gtid; i < KT*CH*36; i += gstride) {
        int k   = i / (CH*36);
        int rem = i - k*(CH*36);
        int co  = rem / 36;
        int p   = rem % 36;
        uint32_t val = 0;
        if (p < 32) {
            float w0 = conv_w[(co*CH + 2*p    )*KT + k];
            float w1 = conv_w[(co*CH + 2*p + 1)*KT + k];
            __half2 h2 = __floats2half2_rn(w0, w1);
            val = *(uint32_t*)&h2;
        }
        g_w2[i] = val;
    }
}

// ============================ GCN (R15 body, dynamic work queue) ============================
#define HS_STR 36
#define WS_STR 36
#define HWT_STR 20
#define AH_STR 20
#define GCN_S 4
#define GCN_GRID 592
#define GCN_GROUPS 2400

__global__ __launch_bounds__(256, 4)
void gcn_kernel(const float* __restrict__ h,
                const float* __restrict__ gcn_b) {
    extern __shared__ __align__(16) char smraw[];
    uint32_t* hs2 = (uint32_t*)smraw;                 // 128*36 (reused as x-staging after GEMM1)
    uint32_t* Ws2 = hs2 + 128*HS_STR;                 // 64*36
    uint32_t* hwT = Ws2 + CH*WS_STR;                  // 256*20
    uint32_t* ah2 = hwT + 256*HWT_STR;                // 32*20
    float*    gb  = (float*)(ah2 + 32*AH_STR);        // 64
    __shared__ int s_g;

    const int tid = threadIdx.x;

    for (int i = tid; i < CH*WS_STR/4; i += 256)
        cp_async16(&Ws2[i*4], &g_gw2[i*4]);
    for (int i = tid; i < 32*AH_STR/4; i += 256)
        cp_async16(&ah2[i*4], &g_ah2[i*4]);
    if (tid < 16)
        cp_async16(&gb[tid*4], &gcn_b[tid*4]);
    CP_COMMIT();
    CP_WAIT0();

    const int lane = tid & 31, w = tid >> 5;
    const int gID = lane >> 2, tig = lane & 3;

    while (true) {
        if (tid == 0) s_g = (int)atomicAdd(&g_gcn_ctr, 1u);
        __syncthreads();   // claim visible; also orders prior iter's staging reads before refill
        const int grp = s_g;
        if (grp >= GCN_GROUPS) break;

        const int g0 = grp * GCN_S;
        const float* hbase = h + (long long)g0 * VJ * CH;

        // hs2 fill, all 128 rows (pads re-zeroed each iter; hs2 was clobbered by staging)
        for (int i = tid; i < 128*16; i += 256) {
            int r = i >> 4, c4 = (i & 15) * 4;
            int s = r >> 5, vv = r & 31;
            uint2 val = make_uint2(0, 0);
            if (vv < VJ) {
                float4 v = *(const float4*)&hbase[(s*VJ + vv)*CH + c4];
                __half2 p0 = __floats2half2_rn(v.x, v.y);
                __half2 p1 = __floats2half2_rn(v.z, v.w);
                val = make_uint2(*(uint32_t*)&p0, *(uint32_t*)&p1);
            }
            *(uint2*)&hs2[r*HS_STR + (i & 15)*2] = val;
        }
        __syncthreads();

        // ---- GEMM1' (fp16): hwT = W^T @ h^T, 8 balanced warps ----
        {
            const int mt = w & 3;
            const int ng = w >> 2;
            float acc[8][4];
#pragma unroll
            for (int nb = 0; nb < 8; nb++)
#pragma unroll
                for (int j = 0; j < 4; j++) acc[nb][j] = 0.f;
#pragma unroll
            for (int kk = 0; kk < 4; kk++) {
                int abase = (mt*16 + gID)*WS_STR + kk*8 + tig;
                uint32_t a[4];
                a[0] = Ws2[abase];
                a[1] = Ws2[abase + 8*WS_STR];
                a[2] = Ws2[abase + 4];
                a[3] = Ws2[abase + 8*WS_STR + 4];
                const uint32_t* bp = hs2 + (ng*64 + gID)*HS_STR + kk*8 + tig;
#pragma unroll
                for (int nb = 0; nb < 8; nb++) {
                    uint32_t b0 = bp[nb*8*HS_STR];
                    uint32_t b1 = bp[nb*8*HS_STR + 4];
                    mma_f16(acc[nb], a, b0, b1);
                }
            }
#pragma unroll
            for (int nb = 0; nb < 8; nb++) {
                int srow = (ng*2 + (nb >> 2)) * 64 + mt*16 + gID;
                int col  = (nb & 3)*4 + tig;
#pragma unroll
                for (int rr = 0; rr < 2; rr++) {
                    __half2 h2 = __floats2half2_rn(acc[nb][rr*2], acc[nb][rr*2+1]);
                    hwT[(srow + rr*8)*HWT_STR + col] = *(uint32_t*)&h2;
                }
            }
        }
        __syncthreads();   // GEMM1 hs2 reads done -> hs2 reusable as staging

        // ---- GEMM2 (fp16): x = Ah @ hw; stage to smem (conflict-free) ----
        {
            const int s = w >> 1, mt2 = w & 1;
            float acc[8][4];
#pragma unroll
            for (int nb = 0; nb < 8; nb++)
#pragma unroll
                for (int j = 0; j < 4; j++) acc[nb][j] = 0.f;
#pragma unroll
            for (int kk = 0; kk < 2; kk++) {
                int abase = (mt2*16 + gID)*AH_STR + kk*8 + tig;
                uint32_t a[4];
                a[0] = ah2[abase];
                a[1] = ah2[abase + 8*AH_STR];
                a[2] = ah2[abase + 4];
                a[3] = ah2[abase + 8*AH_STR + 4];
                const uint32_t* bp = hwT + (s*64 + gID)*HWT_STR + kk*8 + tig;
#pragma unroll
                for (int nb = 0; nb < 8; nb++) {
                    uint32_t b0 = bp[nb*8*HWT_STR];
                    uint32_t b1 = bp[nb*8*HWT_STR + 4];
                    mma_f16(acc[nb], a, b0, b1);
                }
            }
#pragma unroll
            for (int nb = 0; nb < 8; nb++) {
                int c = nb*8 + tig*2;
                float2 gbv = *(const float2*)&gb[c];
#pragma unroll
                for (int rr = 0; rr < 2; rr++) {
                    int vv = mt2*16 + gID + rr*8;
                    float x0 = fmaxf(acc[nb][rr*2]   + gbv.x, 0.f);
                    float x1 = fmaxf(acc[nb][rr*2+1] + gbv.y, 0.f);
                    __half2 h2 = __floats2half2_rn(x0, x1);
                    hs2[(s*32 + vv)*HS_STR + nb*4 + tig] = *(uint32_t*)&h2;
                }
            }
        }
        __syncthreads();

        // ---- coalesced copy: staging -> g_xg (STG.128 on 128B-aligned rows) ----
        for (int i = tid; i < 100*8; i += 256) {
            int r = i >> 3, chunk = i & 7;
            int s = r / VJ, vv = r - s*VJ;
            uint4 val = *(uint4*)&hs2[(s*32 + vv)*HS_STR + chunk*4];
            int g = g0 + s;
            int nm = g / TLEN, t = g % TLEN;
            *(uint4*)&g_xg[((nm*VJ + vv)*TLEN + t)*CH + chunk*8] = val;
        }
        // next iteration's post-claim __syncthreads orders staging reads vs refill
    }
}

// ============================ Conv (fp16 MMA + ldmatrix) — R15 proven, frozen ============================
#define XSTR_H 72          // halves per X row
#define WSTR_U 36          // u32 per W co row
#define XROWS 168
#define CONV_THREADS 160

__global__ __launch_bounds__(CONV_THREADS, 3)
void conv_mma_kernel(const float* __restrict__ h, float* __restrict__ out) {
    extern __shared__ __align__(16) char smraw[];
    __half*   xs  = (__half*)smraw;                        // 168*72 halves
    uint32_t* wb  = (uint32_t*)(smraw + XROWS*XSTR_H*2);   // 2 * 64*36 u32

    const int tid  = threadIdx.x;
    const int bid  = blockIdx.x;
    const int slab = bid >> 1;
    const int half = bid & 1;
    const int nm = slab / VJ, v = slab % VJ;
    const int tbase = half * 150;
    const __half* xg = g_xg + (long long)slab * TLEN * CH;

    for (int i = tid; i < XROWS*8; i += CONV_THREADS) {
        int r = i >> 3, c8 = (i & 7) * 8;
        int tg = tbase - 4 + r;
        __half* dst = &xs[r*XSTR_H + c8];
        if (r < 158 && tg >= 0 && tg < TLEN)
            cp_async16(dst, xg + tg*CH + c8);
        else
            *(float4*)dst = make_float4(0,0,0,0);
    }
    for (int i = tid; i < CH*WSTR_U/4; i += CONV_THREADS)
        cp_async16(&wb[i*4], &g_w2[i*4]);
    CP_COMMIT();
    CP_WAIT0();
    __syncthreads();

    const int lane = tid & 31, w = tid >> 5;
    const int gID = lane >> 2, tig = lane & 3;

    const uint32_t xs32 = (uint32_t)__cvta_generic_to_shared(xs);
    const uint32_t wb32 = (uint32_t)__cvta_generic_to_shared(wb);
    const int xrow = ((lane >> 3) & 1) * 8 + (lane & 7);
    const int xkof = (lane >> 4) * 8;
    const uint32_t xbase = xs32 + (uint32_t)(((w*32 + xrow)*XSTR_H + xkof) * 2);
    const int bco  = (lane & 7) + ((lane >> 4) << 3);
    const int bkof = ((lane >> 3) & 1) * 4;
    const uint32_t bbase = wb32 + (uint32_t)((bco*WSTR_U + bkof) * 4);

    float acc[2][8][4];
#pragma unroll
    for (int mt = 0; mt < 2; mt++)
#pragma unroll
        for (int nb = 0; nb < 8; nb++)
#pragma unroll
            for (int j = 0; j < 4; j++) acc[mt][nb][j] = 0.f;

    for (int k = 0; k < KT; k++) {
        const uint32_t wsel = (uint32_t)((k & 1) * (CH*WSTR_U*4));
        if (k < KT-1) {
            uint32_t* wnext = wb + ((k+1) & 1) * CH*WSTR_U;
            const uint32_t* wsrc = g_w2 + (k+1)*CH*WSTR_U;
            for (int i = tid; i < CH*WSTR_U/4; i += CONV_THREADS)
                cp_async16(&wnext[i*4], &wsrc[i*4]);
            CP_COMMIT();
        }
        const uint32_t xk = xbase + (uint32_t)(k * (XSTR_H*2));
#pragma unroll
        for (int kk = 0; kk < 4; kk++) {
            uint32_t a0[4], a1[4];
            ldsm_x4(a0, xk + kk*32);
            ldsm_x4(a1, xk + 16*(XSTR_H*2) + kk*32);
            uint32_t bf[4][4];
#pragma unroll
            for (int p = 0; p < 4; p++)
                ldsm_x4(bf[p], bbase + wsel + p*(16*WSTR_U*4) + kk*32);
#pragma unroll
            for (int nb = 0; nb < 8; nb++) {
                uint32_t b0 = bf[nb >> 1][(nb & 1)*2 + 0];
                uint32_t b1 = bf[nb >> 1][(nb & 1)*2 + 1];
                mma_f16(acc[0][nb], a0, b0, b1);
                mma_f16(acc[1][nb], a1, b0, b1);
            }
        }
        if (k < KT-1) {
            CP_WAIT0();
            __syncthreads();
        }
    }

#pragma unroll
    for (int mt = 0; mt < 2; mt++) {
#pragma unroll
        for (int nb = 0; nb < 8; nb++) {
            int co = nb*8 + tig*2;
            float2 scl = *(const float2*)&g_scale[co];
            float2 sft = *(const float2*)&g_shift[co];
#pragma unroll
            for (int rr = 0; rr < 2; rr++) {
                int tl = w*32 + mt*16 + gID + rr*8;
                if (tl >= 150) continue;
                int t = tbase + tl;
                long long o = (((long long)nm*TLEN + t)*VJ + v)*CH + co;
                float x0 = fmaxf(acc[mt][nb][rr*2]  *scl.x + sft.x, 0.f);
                float x1 = fmaxf(acc[mt][nb][rr*2+1]*scl.y + sft.y, 0.f);
                float2 hv = *(const float2*)&h[o];
                *(float2*)&out[o] = make_float2(x0 + hv.x, x1 + hv.y);
            }
        }
    }
}

// ============================ launch ============================
extern "C" void kernel_launch(void* const* d_in, const int* in_sizes, int n_in,
                              void* d_out, int out_size) {
    const float* h        = (const float*)d_in[0];
    const float* adj      = (const float*)d_in[1];
    const float* gcn_w    = (const float*)d_in[2];
    const float* gcn_b    = (const float*)d_in[3];
    const float* conv_w   = (const float*)d_in[4];
    const float* conv_b   = (const float*)d_in[5];
    const float* bn_gamma = (const float*)d_in[6];
    const float* bn_beta  = (const float*)d_in[7];
    const float* bn_mean  = (const float*)d_in[8];
    const float* bn_var   = (const float*)d_in[9];
    float* out = (float*)d_out;

    const int gcn_smem  = (128*HS_STR + CH*WS_STR + 256*HWT_STR + 32*AH_STR)*4 + CH*4;  // ~51 KB
    const int conv_smem = XROWS*XSTR_H*2 + 2*CH*WSTR_U*4;      // 42624 B
    cudaFuncSetAttribute(gcn_kernel,      cudaFuncAttributeMaxDynamicSharedMemorySize, gcn_smem);
    cudaFuncSetAttribute(conv_mma_kernel, cudaFuncAttributeMaxDynamicSharedMemorySize, conv_smem);

    prep_kernel<<<256, 256>>>(adj, gcn_w, conv_w, conv_b, bn_gamma, bn_beta, bn_mean, bn_var);
    gcn_kernel<<<GCN_GRID, 256, gcn_smem>>>(h, gcn_b);
    conv_mma_kernel<<<NMB*VJ*2, CONV_THREADS, conv_smem>>>(h, out);
}